// round 1
// baseline (speedup 1.0000x reference)
#include <cuda_runtime.h>
#include <cuda_bf16.h>

// Problem constants
#define Bn   16
#define Ln   512
#define DBn  3072
#define Dn   300
#define NNn  256
#define NWn  30
#define Hn   256

// GEMM tiling
#define BM 64
#define BN 64
#define BK 32
#define SPAD 4

// Scratch for projected+PReLU'd articles: [B*L, D] = [8192, 300]
__device__ float g_art[Bn * Ln * Dn];

// ---------------------------------------------------------------------------
// Kernel A: art[m, n] = PReLU( sum_k A[m,k] * W[n,k] + bias[n] )
// A: [8192, 3072] row-major, W: [300, 3072] row-major (both K-major -> NT gemm)
// ---------------------------------------------------------------------------
__global__ __launch_bounds__(256) void proj_prelu_kernel(
    const float* __restrict__ A,
    const float* __restrict__ W,
    const float* __restrict__ bias,
    const float* __restrict__ prelu_a)
{
    __shared__ float As[BK][BM + SPAD];
    __shared__ float Ws[BK][BN + SPAD];

    const int tid = threadIdx.x;
    const int tx = tid & 15;        // 0..15  -> n micro-tile
    const int ty = tid >> 4;        // 0..15  -> m micro-tile
    const int m0 = blockIdx.y * BM; // M tiles: 8192/64 = 128
    const int n0 = blockIdx.x * BN; // N tiles: ceil(300/64) = 5

    float acc00=0,acc01=0,acc02=0,acc03=0;
    float acc10=0,acc11=0,acc12=0,acc13=0;
    float acc20=0,acc21=0,acc22=0,acc23=0;
    float acc30=0,acc31=0,acc32=0,acc33=0;

    for (int k0 = 0; k0 < DBn; k0 += BK) {
        // Load A tile: 64 rows x 32 k = 512 float4, 2 per thread
        #pragma unroll
        for (int i = 0; i < 2; i++) {
            int f   = tid + i * 256;
            int row = f >> 3;       // 0..63
            int c4  = f & 7;        // 0..7 (float4 index within 32 k's)
            float4 v = *(const float4*)&A[(size_t)(m0 + row) * DBn + k0 + c4 * 4];
            As[c4*4+0][row] = v.x;
            As[c4*4+1][row] = v.y;
            As[c4*4+2][row] = v.z;
            As[c4*4+3][row] = v.w;
        }
        // Load W tile (guard rows >= 300 with zeros)
        #pragma unroll
        for (int i = 0; i < 2; i++) {
            int f   = tid + i * 256;
            int row = f >> 3;
            int c4  = f & 7;
            int wr  = n0 + row;
            float4 v = make_float4(0.f, 0.f, 0.f, 0.f);
            if (wr < Dn) v = *(const float4*)&W[(size_t)wr * DBn + k0 + c4 * 4];
            Ws[c4*4+0][row] = v.x;
            Ws[c4*4+1][row] = v.y;
            Ws[c4*4+2][row] = v.z;
            Ws[c4*4+3][row] = v.w;
        }
        __syncthreads();

        #pragma unroll
        for (int k = 0; k < BK; k++) {
            float4 a = *(const float4*)&As[k][ty * 4];
            float4 w = *(const float4*)&Ws[k][tx * 4];
            acc00 += a.x * w.x; acc01 += a.x * w.y; acc02 += a.x * w.z; acc03 += a.x * w.w;
            acc10 += a.y * w.x; acc11 += a.y * w.y; acc12 += a.y * w.z; acc13 += a.y * w.w;
            acc20 += a.z * w.x; acc21 += a.z * w.y; acc22 += a.z * w.z; acc23 += a.z * w.w;
            acc30 += a.w * w.x; acc31 += a.w * w.y; acc32 += a.w * w.z; acc33 += a.w * w.w;
        }
        __syncthreads();
    }

    const float pa = prelu_a[0];
    float accs[4][4] = {
        {acc00, acc01, acc02, acc03},
        {acc10, acc11, acc12, acc13},
        {acc20, acc21, acc22, acc23},
        {acc30, acc31, acc32, acc33}};

    #pragma unroll
    for (int i = 0; i < 4; i++) {
        const int m = m0 + ty * 4 + i;
        #pragma unroll
        for (int j = 0; j < 4; j++) {
            const int n = n0 + tx * 4 + j;
            if (n < Dn) {
                float v = accs[i][j] + bias[n];
                v = (v > 0.f) ? v : pa * v;
                g_art[(size_t)m * Dn + n] = v;
            }
        }
    }
}

// ---------------------------------------------------------------------------
// Kernel B: per block, NB nodes of one batch:
//   pooled[n] = masked mean of gathered art rows
//   h[n]      = relu(W1 @ pooled[n] + b1)       (each thread owns one W1 row)
//   out[n]    = W2 . h[n] + b2
// ---------------------------------------------------------------------------
#define NB 16

__global__ __launch_bounds__(256) void node_head_kernel(
    const int*   __restrict__ nodes_idx,
    const int*   __restrict__ nmask,
    const float* __restrict__ W1,
    const float* __restrict__ b1,
    const float* __restrict__ W2,
    const float* __restrict__ b2,
    float*       __restrict__ out)
{
    __shared__ float pooled[NB][Dn + 4];   // 304-float rows (16B aligned)
    __shared__ float s_h[NB][Hn + 4];
    __shared__ int   s_idx[NB][32];
    __shared__ float s_msk[NB][32];
    __shared__ float s_inv[NB];

    const int tid = threadIdx.x;
    const int groups_per_batch = NNn / NB;              // 16
    const int b  = blockIdx.x / groups_per_batch;
    const int g  = blockIdx.x % groups_per_batch;
    const int n0 = g * NB;                              // node offset within batch

    // Load span indices & masks for NB nodes
    for (int e = tid; e < NB * NWn; e += 256) {
        int n = e / NWn, w = e % NWn;
        int base = ((b * NNn) + n0 + n) * NWn + w;
        s_idx[n][w] = nodes_idx[base];
        s_msk[n][w] = (float)nmask[base];
    }
    __syncthreads();

    if (tid < NB) {
        float c = 0.f;
        #pragma unroll
        for (int w = 0; w < NWn; w++) c += s_msk[tid][w];
        s_inv[tid] = 1.0f / fmaxf(c, 1.0f);
    }
    __syncthreads();

    // Masked-mean pooling (art rows are L2-resident: 9.8MB)
    const float* artb = g_art + (size_t)b * Ln * Dn;
    for (int e = tid; e < NB * Dn; e += 256) {
        int n = e / Dn, d = e % Dn;
        float s = 0.f;
        #pragma unroll
        for (int w = 0; w < NWn; w++) {
            s += s_msk[n][w] * artb[(size_t)s_idx[n][w] * Dn + d];
        }
        pooled[n][d] = s * s_inv[n];
    }
    __syncthreads();

    // h[n][tid] for all NB nodes: one W1 row per thread, reused NB times
    {
        float acch[NB];
        const float bb = b1[tid];
        #pragma unroll
        for (int n = 0; n < NB; n++) acch[n] = bb;

        const float* w1r = W1 + (size_t)tid * Dn;
        #pragma unroll 5
        for (int d = 0; d < Dn; d += 4) {
            float4 w4 = *(const float4*)&w1r[d];
            #pragma unroll
            for (int n = 0; n < NB; n++) {
                float4 p4 = *(const float4*)&pooled[n][d];   // warp-broadcast LDS
                acch[n] += w4.x * p4.x + w4.y * p4.y + w4.z * p4.z + w4.w * p4.w;
            }
        }
        #pragma unroll
        for (int n = 0; n < NB; n++) s_h[n][tid] = fmaxf(acch[n], 0.f);
    }
    __syncthreads();

    // out[n] = b2 + sum_t W2[t] * h[n][t]
    const int warp = tid >> 5, lane = tid & 31;
    for (int n = warp; n < NB; n += 8) {
        float s = 0.f;
        #pragma unroll
        for (int t = lane; t < Hn; t += 32) s += W2[t] * s_h[n][t];
        #pragma unroll
        for (int o = 16; o > 0; o >>= 1) s += __shfl_down_sync(0xffffffffu, s, o);
        if (lane == 0) out[b * NNn + n0 + n] = s + b2[0];
    }
}

// ---------------------------------------------------------------------------
extern "C" void kernel_launch(void* const* d_in, const int* in_sizes, int n_in,
                              void* d_out, int out_size)
{
    const float* articles  = (const float*)d_in[0];
    const int*   nodes_idx = (const int*)  d_in[1];
    const int*   nmask     = (const int*)  d_in[2];
    // d_in[3], d_in[4] (relations_idx, rmask) are unused: reference discards edges
    const float* W_bert    = (const float*)d_in[5];
    const float* b_bert    = (const float*)d_in[6];
    const float* prelu_a   = (const float*)d_in[7];
    const float* W1        = (const float*)d_in[8];
    const float* b1        = (const float*)d_in[9];
    const float* W2        = (const float*)d_in[10];
    const float* b2        = (const float*)d_in[11];
    float*       out       = (float*)d_out;

    // Stage 1: projection + PReLU into g_art
    dim3 gridA((Dn + BN - 1) / BN, (Bn * Ln) / BM);   // (5, 128), N-fastest for A L2 reuse
    proj_prelu_kernel<<<gridA, 256>>>(articles, W_bert, b_bert, prelu_a);

    // Stage 2+3: gather-pool + MLP head
    dim3 gridB((Bn * NNn) / NB);                      // 256 blocks
    node_head_kernel<<<gridB, 256>>>(nodes_idx, nmask, W1, b1, W2, b2, out);
}

// round 6
// speedup vs baseline: 1.4561x; 1.4561x over previous
#include <cuda_runtime.h>
#include <cuda_bf16.h>
#include <mma.h>
#include <cstdint>

using namespace nvcuda;

// Problem constants
#define Bn   16
#define Ln   512
#define DBn  3072
#define Dn   300
#define NNn  256
#define NWn  30
#define Hn   256

#define Mtot (Bn * Ln)          // 8192
#define NPAD 320                // 5 N-tiles of 64; cols >=300 computed vs zeros, discarded

// GEMM tiling
#define GBM 128
#define GBN 64
#define GBK 32
#define KP  40                  // smem row pitch in bf16 elements (80 B)
#define NKT (DBn / GBK)         // 96 K-stages

// ONLY device scratch: 9.8 MB (same footprint class as the passing R1 kernel)
__device__ __align__(256) float g_art[Mtot * Dn];

// smem layout (static, 32 KB): bf16 tiles overlaid with fp32 epilogue buffer
#define SM_AHI 0
#define SM_ALO 10240            // 128*40*2
#define SM_WHI 20480
#define SM_WLO 25600            // + 64*40*2
#define SM_BYTES 32768          // epilogue 128x64 fp32 = 32768 (overlay max)

// ---------------------------------------------------------------------------
// Kernel 1: fused split + wmma bf16 3-pass GEMM + bias + PReLU -> g_art
//   art[m,n] = PReLU( sum_k A[m,k]*W[n,k] + bias[n] )
//   fp32 operands split per-tile into bf16 hi/lo; D = Ahi*Whi + Ahi*Wlo + Alo*Whi
// ---------------------------------------------------------------------------
__global__ __launch_bounds__(256) void gemm_fused_kernel(
    const float* __restrict__ A,      // [8192, 3072]
    const float* __restrict__ W,      // [300, 3072]
    const float* __restrict__ bias,
    const float* __restrict__ prelu_a)
{
    __shared__ __align__(32) char smem[SM_BYTES];

    const int tid = threadIdx.x;
    const int wid = tid >> 5;
    const int m0 = blockIdx.y * GBM;
    const int n0 = blockIdx.x * GBN;
    const int wm = wid >> 1;          // 0..3 -> 32-row slices
    const int wn = wid & 1;           // 0..1 -> 32-col slices

    // per-thread load assignment
    const int arow = tid >> 1;        // 0..127
    const int ahalf = tid & 1;        // k in [ahalf*16, +16)
    const int wrow = tid & 63;        // 0..63
    const int wseg = tid >> 6;        // 0..3, k in [wseg*8, +8)
    const bool wvalid = (n0 + wrow) < Dn;

    const float* aptr = A + (size_t)(m0 + arow) * DBn + ahalf * 16;
    const float* wptr = W + (size_t)(n0 + wrow) * DBn + wseg * 8;

    wmma::fragment<wmma::accumulator, 16, 16, 16, float> acc[2][2];
    #pragma unroll
    for (int i = 0; i < 2; i++)
        #pragma unroll
        for (int j = 0; j < 2; j++) wmma::fill_fragment(acc[i][j], 0.0f);

    // register prefetch buffers (fp32)
    float4 aR[4];
    float4 wR[2];
    #pragma unroll
    for (int q = 0; q < 4; q++) aR[q] = ((const float4*)aptr)[q];
    if (wvalid) {
        #pragma unroll
        for (int q = 0; q < 2; q++) wR[q] = ((const float4*)wptr)[q];
    } else {
        wR[0] = wR[1] = make_float4(0.f, 0.f, 0.f, 0.f);
    }

    __nv_bfloat16* sAhi = (__nv_bfloat16*)(smem + SM_AHI);
    __nv_bfloat16* sAlo = (__nv_bfloat16*)(smem + SM_ALO);
    __nv_bfloat16* sWhi = (__nv_bfloat16*)(smem + SM_WHI);
    __nv_bfloat16* sWlo = (__nv_bfloat16*)(smem + SM_WLO);

    for (int t = 0; t < NKT; t++) {
        __syncthreads();   // previous mma done reading smem

        // convert prefetched fp32 -> bf16 hi/lo, store to smem
        {
            // A: 16 values -> 8 packed hi + 8 packed lo
            uint32_t ph[8], pl[8];
            const float* af = (const float*)aR;
            #pragma unroll
            for (int q = 0; q < 8; q++) {
                float x0 = af[2 * q], x1 = af[2 * q + 1];
                __nv_bfloat16 h0 = __float2bfloat16(x0);
                __nv_bfloat16 h1 = __float2bfloat16(x1);
                __nv_bfloat16 l0 = __float2bfloat16(x0 - __bfloat162float(h0));
                __nv_bfloat16 l1 = __float2bfloat16(x1 - __bfloat162float(h1));
                __nv_bfloat162 hh; hh.x = h0; hh.y = h1;
                __nv_bfloat162 ll; ll.x = l0; ll.y = l1;
                ph[q] = *(uint32_t*)&hh;
                pl[q] = *(uint32_t*)&ll;
            }
            uint4* dsth = (uint4*)(sAhi + arow * KP + ahalf * 16);
            uint4* dstl = (uint4*)(sAlo + arow * KP + ahalf * 16);
            dsth[0] = make_uint4(ph[0], ph[1], ph[2], ph[3]);
            dsth[1] = make_uint4(ph[4], ph[5], ph[6], ph[7]);
            dstl[0] = make_uint4(pl[0], pl[1], pl[2], pl[3]);
            dstl[1] = make_uint4(pl[4], pl[5], pl[6], pl[7]);

            // W: 8 values -> 4 packed hi + 4 packed lo
            uint32_t qh[4], ql[4];
            const float* wf = (const float*)wR;
            #pragma unroll
            for (int q = 0; q < 4; q++) {
                float x0 = wf[2 * q], x1 = wf[2 * q + 1];
                __nv_bfloat16 h0 = __float2bfloat16(x0);
                __nv_bfloat16 h1 = __float2bfloat16(x1);
                __nv_bfloat16 l0 = __float2bfloat16(x0 - __bfloat162float(h0));
                __nv_bfloat16 l1 = __float2bfloat16(x1 - __bfloat162float(h1));
                __nv_bfloat162 hh; hh.x = h0; hh.y = h1;
                __nv_bfloat162 ll; ll.x = l0; ll.y = l1;
                qh[q] = *(uint32_t*)&hh;
                ql[q] = *(uint32_t*)&ll;
            }
            *(uint4*)(sWhi + wrow * KP + wseg * 8) = make_uint4(qh[0], qh[1], qh[2], qh[3]);
            *(uint4*)(sWlo + wrow * KP + wseg * 8) = make_uint4(ql[0], ql[1], ql[2], ql[3]);
        }

        // issue next stage's global loads (latency hides under the mma below)
        if (t + 1 < NKT) {
            const float* ap = aptr + (t + 1) * GBK;
            #pragma unroll
            for (int q = 0; q < 4; q++) aR[q] = ((const float4*)ap)[q];
            if (wvalid) {
                const float* wp = wptr + (t + 1) * GBK;
                #pragma unroll
                for (int q = 0; q < 2; q++) wR[q] = ((const float4*)wp)[q];
            }
        }

        __syncthreads();   // smem tiles visible to all warps

        #pragma unroll
        for (int kk = 0; kk < GBK; kk += 16) {
            wmma::fragment<wmma::matrix_a, 16, 16, 16, __nv_bfloat16, wmma::row_major> ah[2], al[2];
            wmma::fragment<wmma::matrix_b, 16, 16, 16, __nv_bfloat16, wmma::col_major> bh[2], bl[2];
            #pragma unroll
            for (int i = 0; i < 2; i++) {
                const int mo = (wm * 32 + i * 16) * KP + kk;
                wmma::load_matrix_sync(ah[i], sAhi + mo, KP);
                wmma::load_matrix_sync(al[i], sAlo + mo, KP);
            }
            #pragma unroll
            for (int j = 0; j < 2; j++) {
                const int no = (wn * 32 + j * 16) * KP + kk;   // col_major: B[k][n] at n*ldb+k
                wmma::load_matrix_sync(bh[j], sWhi + no, KP);
                wmma::load_matrix_sync(bl[j], sWlo + no, KP);
            }
            #pragma unroll
            for (int i = 0; i < 2; i++)
                #pragma unroll
                for (int j = 0; j < 2; j++) {
                    wmma::mma_sync(acc[i][j], ah[i], bh[j], acc[i][j]);
                    wmma::mma_sync(acc[i][j], ah[i], bl[j], acc[i][j]);
                    wmma::mma_sync(acc[i][j], al[i], bh[j], acc[i][j]);
                }
        }
    }

    // epilogue: stage accum in smem (overlay), bias+PReLU, write g_art
    __syncthreads();
    float* ep = (float*)smem;   // 128 x 64, pitch 64
    #pragma unroll
    for (int i = 0; i < 2; i++)
        #pragma unroll
        for (int j = 0; j < 2; j++)
            wmma::store_matrix_sync(ep + (wm * 32 + i * 16) * 64 + wn * 32 + j * 16,
                                    acc[i][j], 64, wmma::mem_row_major);
    __syncthreads();

    const float pa = prelu_a[0];
    for (int e = tid; e < GBM * GBN; e += 256) {
        int m = e >> 6, n = e & 63;
        int gn = n0 + n;
        if (gn < Dn) {
            float v = ep[e] + bias[gn];
            v = (v > 0.f) ? v : pa * v;
            g_art[(size_t)(m0 + m) * Dn + gn] = v;
        }
    }
}

// ---------------------------------------------------------------------------
// Kernel 2: gather-pool + MLP head (R1-proven, 63us)
// ---------------------------------------------------------------------------
#define NB 16

__global__ __launch_bounds__(256) void node_head_kernel(
    const int*   __restrict__ nodes_idx,
    const int*   __restrict__ nmask,
    const float* __restrict__ W1,
    const float* __restrict__ b1,
    const float* __restrict__ W2,
    const float* __restrict__ b2,
    float*       __restrict__ out)
{
    __shared__ float pooled[NB][Dn + 4];
    __shared__ float s_h[NB][Hn + 4];
    __shared__ int   s_idx[NB][32];
    __shared__ float s_msk[NB][32];
    __shared__ float s_inv[NB];

    const int tid = threadIdx.x;
    const int groups_per_batch = NNn / NB;
    const int b  = blockIdx.x / groups_per_batch;
    const int g  = blockIdx.x % groups_per_batch;
    const int n0 = g * NB;

    for (int e = tid; e < NB * NWn; e += 256) {
        int n = e / NWn, w = e % NWn;
        int base = ((b * NNn) + n0 + n) * NWn + w;
        s_idx[n][w] = nodes_idx[base];
        s_msk[n][w] = (float)nmask[base];
    }
    __syncthreads();

    if (tid < NB) {
        float c = 0.f;
        #pragma unroll
        for (int w = 0; w < NWn; w++) c += s_msk[tid][w];
        s_inv[tid] = 1.0f / fmaxf(c, 1.0f);
    }
    __syncthreads();

    const float* artb = g_art + (size_t)b * Ln * Dn;
    for (int e = tid; e < NB * Dn; e += 256) {
        int n = e / Dn, d = e % Dn;
        float s = 0.f;
        #pragma unroll
        for (int w = 0; w < NWn; w++)
            s += s_msk[n][w] * artb[(size_t)s_idx[n][w] * Dn + d];
        pooled[n][d] = s * s_inv[n];
    }
    __syncthreads();

    {
        float acch[NB];
        const float bb = b1[tid];
        #pragma unroll
        for (int n = 0; n < NB; n++) acch[n] = bb;

        const float* w1r = W1 + (size_t)tid * Dn;
        #pragma unroll 5
        for (int d = 0; d < Dn; d += 4) {
            float4 w4 = *(const float4*)&w1r[d];
            #pragma unroll
            for (int n = 0; n < NB; n++) {
                float4 p4 = *(const float4*)&pooled[n][d];
                acch[n] += w4.x * p4.x + w4.y * p4.y + w4.z * p4.z + w4.w * p4.w;
            }
        }
        #pragma unroll
        for (int n = 0; n < NB; n++) s_h[n][tid] = fmaxf(acch[n], 0.f);
    }
    __syncthreads();

    const int warp = tid >> 5, lane = tid & 31;
    for (int n = warp; n < NB; n += 8) {
        float s = 0.f;
        #pragma unroll
        for (int t = lane; t < Hn; t += 32) s += W2[t] * s_h[n][t];
        #pragma unroll
        for (int o = 16; o > 0; o >>= 1) s += __shfl_down_sync(0xffffffffu, s, o);
        if (lane == 0) out[b * NNn + n0 + n] = s + b2[0];
    }
}

// ---------------------------------------------------------------------------
extern "C" void kernel_launch(void* const* d_in, const int* in_sizes, int n_in,
                              void* d_out, int out_size)
{
    const float* articles  = (const float*)d_in[0];
    const int*   nodes_idx = (const int*)  d_in[1];
    const int*   nmask     = (const int*)  d_in[2];
    // d_in[3], d_in[4] (relations) unused: reference discards edges
    const float* W_bert    = (const float*)d_in[5];
    const float* b_bert    = (const float*)d_in[6];
    const float* prelu_a   = (const float*)d_in[7];
    const float* W1        = (const float*)d_in[8];
    const float* b1        = (const float*)d_in[9];
    const float* W2        = (const float*)d_in[10];
    const float* b2        = (const float*)d_in[11];
    float*       out       = (float*)d_out;

    // Stage 1: fused split + wmma GEMM + bias + PReLU
    dim3 gridG(NPAD / GBN, Mtot / GBM);   // (5, 64)
    gemm_fused_kernel<<<gridG, 256>>>(articles, W_bert, b_bert, prelu_a);

    // Stage 2: gather-pool + head
    node_head_kernel<<<(Bn * NNn) / NB, 256>>>(nodes_idx, nmask, W1, b1, W2, b2, out);
}

// round 7
// speedup vs baseline: 1.8413x; 1.2645x over previous
#include <cuda_runtime.h>
#include <cuda_bf16.h>
#include <mma.h>
#include <cstdint>

using namespace nvcuda;

// Problem constants
#define Bn   16
#define Ln   512
#define DBn  3072
#define Dn   300
#define NNn  256
#define NWn  30
#define Hn   256

#define Mtot (Bn * Ln)          // 8192
#define NPAD 320                // 5 N-tiles of 64

// GEMM tiling
#define GBM 128
#define GBN 64
#define GBK 32
#define KP  40                  // smem pitch in bf16 (80 B: conflict-free LDSM, 5*16B)
#define NKT (DBn / GBK)         // 96 K-stages

// Device scratch: g_art 9.8 MB + W split 3.9 MB (proven-safe footprint class)
__device__ __align__(256) float         g_art[Mtot * Dn];
__device__ __align__(256) __nv_bfloat16 g_Whi[NPAD * DBn];
__device__ __align__(256) __nv_bfloat16 g_Wlo[NPAD * DBn];

__device__ __forceinline__ uint32_t smem_u32(const void* p) {
    uint32_t a;
    asm("{ .reg .u64 t; cvta.to.shared.u64 t, %1; cvt.u32.u64 %0, t; }" : "=r"(a) : "l"(p));
    return a;
}
__device__ __forceinline__ void cp_async16(uint32_t dst, const void* src) {
    asm volatile("cp.async.cg.shared.global [%0], [%1], 16;" :: "r"(dst), "l"(src));
}

// pack 2 fp32 -> bf16x2 (lo = x0), and residuals
__device__ __forceinline__ void split2(float x0, float x1, uint32_t& h, uint32_t& l) {
    __nv_bfloat162 hh = __float22bfloat162_rn(make_float2(x0, x1));
    h = *(uint32_t*)&hh;
    float h0 = __uint_as_float(h << 16);
    float h1 = __uint_as_float(h & 0xffff0000u);
    __nv_bfloat162 ll = __float22bfloat162_rn(make_float2(x0 - h0, x1 - h1));
    l = *(uint32_t*)&ll;
}

// ---------------------------------------------------------------------------
// Kernel 0: split W fp32 -> bf16 hi/lo, padded to 320 rows (pad rows zero)
// ---------------------------------------------------------------------------
#define NWP4 (NPAD * DBn / 4)       // 245760 float4-slots in padded space

__global__ __launch_bounds__(256) void split_w_kernel(const float* __restrict__ W)
{
    int i = blockIdx.x * 256 + threadIdx.x;
    if (i >= NWP4) return;
    int row = (i * 4) / DBn;
    float4 v = make_float4(0.f, 0.f, 0.f, 0.f);
    if (row < Dn) v = reinterpret_cast<const float4*>(W)[i];   // same linear index
    uint32_t h01, l01, h23, l23;
    split2(v.x, v.y, h01, l01);
    split2(v.z, v.w, h23, l23);
    reinterpret_cast<uint2*>(g_Whi)[i] = make_uint2(h01, h23);
    reinterpret_cast<uint2*>(g_Wlo)[i] = make_uint2(l01, l23);
}

// ---------------------------------------------------------------------------
// Kernel 1: fused A-split + wmma bf16 3-pass GEMM + bias + PReLU -> g_art
// smem: A subs (buf*2+hl) @ 10240 B each (4), W subs @ 5120 B each (4) = 60 KB
// ---------------------------------------------------------------------------
#define ASUB 10240
#define WSUB 5120
#define SM_A 0
#define SM_W (4 * ASUB)             // 40960
#define SMEMG (SM_W + 4 * WSUB)     // 61440

__global__ __launch_bounds__(256) void gemm_fused2_kernel(
    const float* __restrict__ A,
    const float* __restrict__ bias,
    const float* __restrict__ prelu_a)
{
    extern __shared__ char smem[];
    const uint32_t sb = smem_u32(smem);
    const int tid = threadIdx.x;
    const int wid = tid >> 5;
    const int m0 = blockIdx.y * GBM;
    const int n0 = blockIdx.x * GBN;
    const int wm = wid >> 1;          // 0..3
    const int wn = wid & 1;           // 0..1

    // A load/convert assignment: 16 fp32 per thread
    const int arow = tid >> 1;        // 0..127
    const int ahalf = tid & 1;        // k within [ahalf*16, +16)
    const float* aptr = A + (size_t)(m0 + arow) * DBn + ahalf * 16;

    // W cp.async assignment: 2 chunks of 16B per thread per hl
    const int wrow = tid >> 2;        // 0..63
    const int wseg = tid & 3;         // 0..3

    wmma::fragment<wmma::accumulator, 16, 16, 16, float> acc[2][2];
    #pragma unroll
    for (int i = 0; i < 2; i++)
        #pragma unroll
        for (int j = 0; j < 2; j++) wmma::fill_fragment(acc[i][j], 0.0f);

    auto cp_w_stage = [&](int t, int buf) {
        const int k0 = t * GBK;
        #pragma unroll
        for (int hl = 0; hl < 2; hl++) {
            const __nv_bfloat16* src = hl ? g_Wlo : g_Whi;
            uint32_t dst = sb + SM_W + (uint32_t)((buf * 2 + hl) * WSUB);
            cp_async16(dst + (uint32_t)(wrow * (KP * 2) + wseg * 16),
                       src + (size_t)(n0 + wrow) * DBn + k0 + wseg * 8);
        }
        asm volatile("cp.async.commit_group;");
    };

    auto convert_a = [&](const float4* aR, int buf) {
        uint32_t ph[8], pl[8];
        const float* af = (const float*)aR;
        #pragma unroll
        for (int q = 0; q < 8; q++)
            split2(af[2 * q], af[2 * q + 1], ph[q], pl[q]);
        uint4* dh = (uint4*)(smem + SM_A + (buf * 2 + 0) * ASUB) ;
        uint4* dl = (uint4*)(smem + SM_A + (buf * 2 + 1) * ASUB);
        const int off16 = (arow * (KP * 2) + ahalf * 32) >> 4;  // uint4 index
        dh[off16 + 0] = make_uint4(ph[0], ph[1], ph[2], ph[3]);
        dh[off16 + 1] = make_uint4(ph[4], ph[5], ph[6], ph[7]);
        dl[off16 + 0] = make_uint4(pl[0], pl[1], pl[2], pl[3]);
        dl[off16 + 1] = make_uint4(pl[4], pl[5], pl[6], pl[7]);
    };

    // ---- prologue: stage 0 ----
    float4 aR[4];
    #pragma unroll
    for (int q = 0; q < 4; q++) aR[q] = ((const float4*)aptr)[q];
    cp_w_stage(0, 0);
    convert_a(aR, 0);
    {
        const float* ap = aptr + GBK;          // A(1)
        #pragma unroll
        for (int q = 0; q < 4; q++) aR[q] = ((const float4*)ap)[q];
    }
    asm volatile("cp.async.wait_group 0;");
    __syncthreads();

    // ---- main loop ----
    for (int t = 0; t < NKT; t++) {
        const int b = t & 1;
        if (t + 1 < NKT) cp_w_stage(t + 1, b ^ 1);

        // mma over buf b (HMMAs issue to tensor pipe; results consumed at epilogue)
        {
            const __nv_bfloat16* sAhi = (const __nv_bfloat16*)(smem + SM_A + (b * 2 + 0) * ASUB);
            const __nv_bfloat16* sAlo = (const __nv_bfloat16*)(smem + SM_A + (b * 2 + 1) * ASUB);
            const __nv_bfloat16* sWhi = (const __nv_bfloat16*)(smem + SM_W + (b * 2 + 0) * WSUB);
            const __nv_bfloat16* sWlo = (const __nv_bfloat16*)(smem + SM_W + (b * 2 + 1) * WSUB);
            #pragma unroll
            for (int kk = 0; kk < GBK; kk += 16) {
                wmma::fragment<wmma::matrix_a, 16, 16, 16, __nv_bfloat16, wmma::row_major> ah[2], al[2];
                wmma::fragment<wmma::matrix_b, 16, 16, 16, __nv_bfloat16, wmma::col_major> bh[2], bl[2];
                #pragma unroll
                for (int i = 0; i < 2; i++) {
                    const int mo = (wm * 32 + i * 16) * KP + kk;
                    wmma::load_matrix_sync(ah[i], sAhi + mo, KP);
                    wmma::load_matrix_sync(al[i], sAlo + mo, KP);
                }
                #pragma unroll
                for (int j = 0; j < 2; j++) {
                    const int no = (wn * 32 + j * 16) * KP + kk;
                    wmma::load_matrix_sync(bh[j], sWhi + no, KP);
                    wmma::load_matrix_sync(bl[j], sWlo + no, KP);
                }
                #pragma unroll
                for (int i = 0; i < 2; i++)
                    #pragma unroll
                    for (int j = 0; j < 2; j++) {
                        wmma::mma_sync(acc[i][j], ah[i], bh[j], acc[i][j]);
                        wmma::mma_sync(acc[i][j], ah[i], bl[j], acc[i][j]);
                        wmma::mma_sync(acc[i][j], al[i], bh[j], acc[i][j]);
                    }
            }
        }

        // convert A(t+1) into the other buffer (overlaps tensor-pipe drain)
        if (t + 1 < NKT) {
            convert_a(aR, b ^ 1);
            if (t + 2 < NKT) {
                const float* ap = aptr + (size_t)(t + 2) * GBK;
                #pragma unroll
                for (int q = 0; q < 4; q++) aR[q] = ((const float4*)ap)[q];
            }
            asm volatile("cp.async.wait_group 0;");   // W(t+1) resident
        }
        __syncthreads();
    }

    // ---- epilogue: overlay smem (first 32 KB), bias + PReLU, store ----
    float* ep = (float*)smem;   // 128 x 64, pitch 64
    #pragma unroll
    for (int i = 0; i < 2; i++)
        #pragma unroll
        for (int j = 0; j < 2; j++)
            wmma::store_matrix_sync(ep + (wm * 32 + i * 16) * 64 + wn * 32 + j * 16,
                                    acc[i][j], 64, wmma::mem_row_major);
    __syncthreads();

    const float pa = prelu_a[0];
    for (int e = tid; e < GBM * GBN; e += 256) {
        int m = e >> 6, n = e & 63;
        int gn = n0 + n;
        if (gn < Dn) {
            float v = ep[e] + bias[gn];
            v = (v > 0.f) ? v : pa * v;
            g_art[(size_t)(m0 + m) * Dn + gn] = v;
        }
    }
}

// ---------------------------------------------------------------------------
// Kernel 2: gather-pool + MLP head (R1-proven, 63us)
// ---------------------------------------------------------------------------
#define NB 16

__global__ __launch_bounds__(256) void node_head_kernel(
    const int*   __restrict__ nodes_idx,
    const int*   __restrict__ nmask,
    const float* __restrict__ W1,
    const float* __restrict__ b1,
    const float* __restrict__ W2,
    const float* __restrict__ b2,
    float*       __restrict__ out)
{
    __shared__ float pooled[NB][Dn + 4];
    __shared__ float s_h[NB][Hn + 4];
    __shared__ int   s_idx[NB][32];
    __shared__ float s_msk[NB][32];
    __shared__ float s_inv[NB];

    const int tid = threadIdx.x;
    const int groups_per_batch = NNn / NB;
    const int b  = blockIdx.x / groups_per_batch;
    const int g  = blockIdx.x % groups_per_batch;
    const int n0 = g * NB;

    for (int e = tid; e < NB * NWn; e += 256) {
        int n = e / NWn, w = e % NWn;
        int base = ((b * NNn) + n0 + n) * NWn + w;
        s_idx[n][w] = nodes_idx[base];
        s_msk[n][w] = (float)nmask[base];
    }
    __syncthreads();

    if (tid < NB) {
        float c = 0.f;
        #pragma unroll
        for (int w = 0; w < NWn; w++) c += s_msk[tid][w];
        s_inv[tid] = 1.0f / fmaxf(c, 1.0f);
    }
    __syncthreads();

    const float* artb = g_art + (size_t)b * Ln * Dn;
    for (int e = tid; e < NB * Dn; e += 256) {
        int n = e / Dn, d = e % Dn;
        float s = 0.f;
        #pragma unroll
        for (int w = 0; w < NWn; w++)
            s += s_msk[n][w] * artb[(size_t)s_idx[n][w] * Dn + d];
        pooled[n][d] = s * s_inv[n];
    }
    __syncthreads();

    {
        float acch[NB];
        const float bb = b1[tid];
        #pragma unroll
        for (int n = 0; n < NB; n++) acch[n] = bb;

        const float* w1r = W1 + (size_t)tid * Dn;
        #pragma unroll 5
        for (int d = 0; d < Dn; d += 4) {
            float4 w4 = *(const float4*)&w1r[d];
            #pragma unroll
            for (int n = 0; n < NB; n++) {
                float4 p4 = *(const float4*)&pooled[n][d];
                acch[n] += w4.x * p4.x + w4.y * p4.y + w4.z * p4.z + w4.w * p4.w;
            }
        }
        #pragma unroll
        for (int n = 0; n < NB; n++) s_h[n][tid] = fmaxf(acch[n], 0.f);
    }
    __syncthreads();

    const int warp = tid >> 5, lane = tid & 31;
    for (int n = warp; n < NB; n += 8) {
        float s = 0.f;
        #pragma unroll
        for (int t = lane; t < Hn; t += 32) s += W2[t] * s_h[n][t];
        #pragma unroll
        for (int o = 16; o > 0; o >>= 1) s += __shfl_down_sync(0xffffffffu, s, o);
        if (lane == 0) out[b * NNn + n0 + n] = s + b2[0];
    }
}

// ---------------------------------------------------------------------------
extern "C" void kernel_launch(void* const* d_in, const int* in_sizes, int n_in,
                              void* d_out, int out_size)
{
    const float* articles  = (const float*)d_in[0];
    const int*   nodes_idx = (const int*)  d_in[1];
    const int*   nmask     = (const int*)  d_in[2];
    // d_in[3], d_in[4] (relations) unused: reference discards edges
    const float* W_bert    = (const float*)d_in[5];
    const float* b_bert    = (const float*)d_in[6];
    const float* prelu_a   = (const float*)d_in[7];
    const float* W1        = (const float*)d_in[8];
    const float* b1        = (const float*)d_in[9];
    const float* W2        = (const float*)d_in[10];
    const float* b2        = (const float*)d_in[11];
    float*       out       = (float*)d_out;

    // Idempotent, called every time (no static guards).
    cudaFuncSetAttribute(gemm_fused2_kernel,
                         cudaFuncAttributeMaxDynamicSharedMemorySize, SMEMG);

    // Stage 0: W split (tiny)
    split_w_kernel<<<(NWP4 + 255) / 256, 256>>>(W_bert);

    // Stage 1: fused A-split + wmma GEMM + bias + PReLU
    dim3 gridG(NPAD / GBN, Mtot / GBM);   // (5, 64)
    gemm_fused2_kernel<<<gridG, 256, SMEMG>>>(articles, b_bert, prelu_a);

    // Stage 2: gather-pool + head
    node_head_kernel<<<(Bn * NNn) / NB, 256>>>(nodes_idx, nmask, W1, b1, W2, b2, out);
}

// round 8
// speedup vs baseline: 2.4878x; 1.3511x over previous
#include <cuda_runtime.h>
#include <cuda_bf16.h>
#include <mma.h>
#include <cstdint>

using namespace nvcuda;

// Problem constants
#define Bn   16
#define Ln   512
#define DBn  3072
#define Dn   300
#define NNn  256
#define NWn  30
#define Hn   256

#define Mtot (Bn * Ln)          // 8192
#define NPAD 320                // 2 N-tiles of 160

// GEMM tiling
#define GBM 128
#define GBN 160
#define GBK 32
#define KP  40                  // smem pitch in bf16 (80 B)
#define NKT (DBn / GBK)         // 96 K-stages

// Device scratch: g_art 9.8 MB + W split 3.9 MB
__device__ __align__(256) float         g_art[Mtot * Dn];
__device__ __align__(256) __nv_bfloat16 g_Whi[NPAD * DBn];
__device__ __align__(256) __nv_bfloat16 g_Wlo[NPAD * DBn];

__device__ __forceinline__ void cp_async16(uint32_t dst, const void* src) {
    asm volatile("cp.async.cg.shared.global [%0], [%1], 16;" :: "r"(dst), "l"(src));
}
__device__ __forceinline__ uint32_t smem_u32(const void* p) {
    uint32_t a;
    asm("{ .reg .u64 t; cvta.to.shared.u64 t, %1; cvt.u32.u64 %0, t; }" : "=r"(a) : "l"(p));
    return a;
}

// pack 2 fp32 -> bf16x2 hi + bf16x2 residual
__device__ __forceinline__ void split2(float x0, float x1, uint32_t& h, uint32_t& l) {
    __nv_bfloat162 hh = __float22bfloat162_rn(make_float2(x0, x1));
    h = *(uint32_t*)&hh;
    float h0 = __uint_as_float(h << 16);
    float h1 = __uint_as_float(h & 0xffff0000u);
    __nv_bfloat162 ll = __float22bfloat162_rn(make_float2(x0 - h0, x1 - h1));
    l = *(uint32_t*)&ll;
}

// ---------------------------------------------------------------------------
// Kernel 0: split W fp32 -> bf16 hi/lo, padded to 320 rows (pad rows zero)
// ---------------------------------------------------------------------------
#define NWP4 (NPAD * DBn / 4)       // 245760

__global__ __launch_bounds__(256) void split_w_kernel(const float* __restrict__ W)
{
    int i = blockIdx.x * 256 + threadIdx.x;
    if (i >= NWP4) return;
    int row = (i * 4) / DBn;
    float4 v = make_float4(0.f, 0.f, 0.f, 0.f);
    if (row < Dn) v = reinterpret_cast<const float4*>(W)[i];
    uint32_t h01, l01, h23, l23;
    split2(v.x, v.y, h01, l01);
    split2(v.z, v.w, h23, l23);
    reinterpret_cast<uint2*>(g_Whi)[i] = make_uint2(h01, h23);
    reinterpret_cast<uint2*>(g_Wlo)[i] = make_uint2(l01, l23);
}

// ---------------------------------------------------------------------------
// Kernel 1: fused A-split + wmma bf16 3-pass GEMM + bias + PReLU -> g_art
// grid (2, 64) = 128 CTAs -> ONE wave on 148 SMs
// smem: A subs (buf*2+hl) @ 10240 B x4 = 40960; W subs @ 12800 B x4 = 51200
// ---------------------------------------------------------------------------
#define ASUB 10240                  // 128*40*2
#define WSUB 12800                  // 160*40*2
#define SM_A 0
#define SM_W (4 * ASUB)             // 40960
#define SMEMG (SM_W + 4 * WSUB)     // 92160 (epilogue 128x160 f32 = 81920 overlays)

__global__ __launch_bounds__(256) void gemm_fused3_kernel(
    const float* __restrict__ A,
    const float* __restrict__ bias,
    const float* __restrict__ prelu_a)
{
    extern __shared__ char smem[];
    const uint32_t sb = smem_u32(smem);
    const int tid = threadIdx.x;
    const int wid = tid >> 5;
    const int m0 = blockIdx.y * GBM;
    const int n0 = blockIdx.x * GBN;
    const int wm = wid >> 1;          // 0..3 -> 32-row slice
    const int wn = wid & 1;           // 0..1 -> 80-col slice

    // A load/convert: 16 fp32 per thread (128 rows x 2 k-halves)
    const int arow = tid >> 1;
    const int ahalf = tid & 1;
    const float* aptr = A + (size_t)(m0 + arow) * DBn + ahalf * 16;

    wmma::fragment<wmma::accumulator, 16, 16, 16, float> acc[2][5];
    #pragma unroll
    for (int i = 0; i < 2; i++)
        #pragma unroll
        for (int j = 0; j < 5; j++) wmma::fill_fragment(acc[i][j], 0.0f);

    // W stage: per hl, 160 rows x 4 segs of 16B = 640 chunks
    auto cp_w_stage = [&](int t, int buf) {
        const int k0 = t * GBK;
        #pragma unroll
        for (int hl = 0; hl < 2; hl++) {
            const __nv_bfloat16* src = hl ? g_Wlo : g_Whi;
            uint32_t dst = sb + SM_W + (uint32_t)((buf * 2 + hl) * WSUB);
            #pragma unroll
            for (int r = 0; r < 3; r++) {
                int i = tid + r * 256;
                if (i < 640) {
                    int row = i >> 2, seg = i & 3;
                    cp_async16(dst + (uint32_t)(row * (KP * 2) + seg * 16),
                               src + (size_t)(n0 + row) * DBn + k0 + seg * 8);
                }
            }
        }
        asm volatile("cp.async.commit_group;");
    };

    auto convert_a = [&](const float4* aR, int buf) {
        uint32_t ph[8], pl[8];
        const float* af = (const float*)aR;
        #pragma unroll
        for (int q = 0; q < 8; q++)
            split2(af[2 * q], af[2 * q + 1], ph[q], pl[q]);
        uint4* dh = (uint4*)(smem + SM_A + (buf * 2 + 0) * ASUB);
        uint4* dl = (uint4*)(smem + SM_A + (buf * 2 + 1) * ASUB);
        const int off16 = (arow * (KP * 2) + ahalf * 32) >> 4;
        dh[off16 + 0] = make_uint4(ph[0], ph[1], ph[2], ph[3]);
        dh[off16 + 1] = make_uint4(ph[4], ph[5], ph[6], ph[7]);
        dl[off16 + 0] = make_uint4(pl[0], pl[1], pl[2], pl[3]);
        dl[off16 + 1] = make_uint4(pl[4], pl[5], pl[6], pl[7]);
    };

    // ---- prologue ----
    float4 aR[4];
    #pragma unroll
    for (int q = 0; q < 4; q++) aR[q] = ((const float4*)aptr)[q];
    cp_w_stage(0, 0);
    convert_a(aR, 0);
    {
        const float* ap = aptr + GBK;
        #pragma unroll
        for (int q = 0; q < 4; q++) aR[q] = ((const float4*)ap)[q];
    }
    asm volatile("cp.async.wait_group 0;");
    __syncthreads();

    // ---- main loop ----
    for (int t = 0; t < NKT; t++) {
        const int b = t & 1;
        if (t + 1 < NKT) cp_w_stage(t + 1, b ^ 1);

        {
            const __nv_bfloat16* sAhi = (const __nv_bfloat16*)(smem + SM_A + (b * 2 + 0) * ASUB);
            const __nv_bfloat16* sAlo = (const __nv_bfloat16*)(smem + SM_A + (b * 2 + 1) * ASUB);
            const __nv_bfloat16* sWhi = (const __nv_bfloat16*)(smem + SM_W + (b * 2 + 0) * WSUB);
            const __nv_bfloat16* sWlo = (const __nv_bfloat16*)(smem + SM_W + (b * 2 + 1) * WSUB);
            #pragma unroll
            for (int kk = 0; kk < GBK; kk += 16) {
                wmma::fragment<wmma::matrix_a, 16, 16, 16, __nv_bfloat16, wmma::row_major> ah[2], al[2];
                #pragma unroll
                for (int i = 0; i < 2; i++) {
                    const int mo = (wm * 32 + i * 16) * KP + kk;
                    wmma::load_matrix_sync(ah[i], sAhi + mo, KP);
                    wmma::load_matrix_sync(al[i], sAlo + mo, KP);
                }
                #pragma unroll
                for (int j = 0; j < 5; j++) {
                    wmma::fragment<wmma::matrix_b, 16, 16, 16, __nv_bfloat16, wmma::col_major> bh, bl;
                    const int no = (wn * 80 + j * 16) * KP + kk;
                    wmma::load_matrix_sync(bh, sWhi + no, KP);
                    wmma::load_matrix_sync(bl, sWlo + no, KP);
                    #pragma unroll
                    for (int i = 0; i < 2; i++) {
                        wmma::mma_sync(acc[i][j], ah[i], bh, acc[i][j]);
                        wmma::mma_sync(acc[i][j], ah[i], bl, acc[i][j]);
                        wmma::mma_sync(acc[i][j], al[i], bh, acc[i][j]);
                    }
                }
            }
        }

        if (t + 1 < NKT) {
            convert_a(aR, b ^ 1);                    // overlaps tensor-pipe drain
            if (t + 2 < NKT) {
                const float* ap = aptr + (size_t)(t + 2) * GBK;
                #pragma unroll
                for (int q = 0; q < 4; q++) aR[q] = ((const float4*)ap)[q];
            }
            asm volatile("cp.async.wait_group 0;");  // W(t+1) resident
        }
        __syncthreads();
    }

    // ---- epilogue: overlay smem, bias + PReLU, store ----
    float* ep = (float*)smem;   // 128 x 160, pitch 160
    #pragma unroll
    for (int i = 0; i < 2; i++)
        #pragma unroll
        for (int j = 0; j < 5; j++)
            wmma::store_matrix_sync(ep + (wm * 32 + i * 16) * 160 + wn * 80 + j * 16,
                                    acc[i][j], 160, wmma::mem_row_major);
    __syncthreads();

    const float pa = prelu_a[0];
    for (int e = tid; e < GBM * GBN; e += 256) {
        int m = e / GBN, n = e % GBN;
        int gn = n0 + n;
        if (gn < Dn) {
            float v = ep[e] + bias[gn];
            v = (v > 0.f) ? v : pa * v;
            g_art[(size_t)(m0 + m) * Dn + gn] = v;
        }
    }
}

// ---------------------------------------------------------------------------
// Kernel 2: gather-pool + MLP head (R1-proven, 63us)
// ---------------------------------------------------------------------------
#define NB 16

__global__ __launch_bounds__(256) void node_head_kernel(
    const int*   __restrict__ nodes_idx,
    const int*   __restrict__ nmask,
    const float* __restrict__ W1,
    const float* __restrict__ b1,
    const float* __restrict__ W2,
    const float* __restrict__ b2,
    float*       __restrict__ out)
{
    __shared__ float pooled[NB][Dn + 4];
    __shared__ float s_h[NB][Hn + 4];
    __shared__ int   s_idx[NB][32];
    __shared__ float s_msk[NB][32];
    __shared__ float s_inv[NB];

    const int tid = threadIdx.x;
    const int groups_per_batch = NNn / NB;
    const int b  = blockIdx.x / groups_per_batch;
    const int g  = blockIdx.x % groups_per_batch;
    const int n0 = g * NB;

    for (int e = tid; e < NB * NWn; e += 256) {
        int n = e / NWn, w = e % NWn;
        int base = ((b * NNn) + n0 + n) * NWn + w;
        s_idx[n][w] = nodes_idx[base];
        s_msk[n][w] = (float)nmask[base];
    }
    __syncthreads();

    if (tid < NB) {
        float c = 0.f;
        #pragma unroll
        for (int w = 0; w < NWn; w++) c += s_msk[tid][w];
        s_inv[tid] = 1.0f / fmaxf(c, 1.0f);
    }
    __syncthreads();

    const float* artb = g_art + (size_t)b * Ln * Dn;
    for (int e = tid; e < NB * Dn; e += 256) {
        int n = e / Dn, d = e % Dn;
        float s = 0.f;
        #pragma unroll
        for (int w = 0; w < NWn; w++)
            s += s_msk[n][w] * artb[(size_t)s_idx[n][w] * Dn + d];
        pooled[n][d] = s * s_inv[n];
    }
    __syncthreads();

    {
        float acch[NB];
        const float bb = b1[tid];
        #pragma unroll
        for (int n = 0; n < NB; n++) acch[n] = bb;

        const float* w1r = W1 + (size_t)tid * Dn;
        #pragma unroll 5
        for (int d = 0; d < Dn; d += 4) {
            float4 w4 = *(const float4*)&w1r[d];
            #pragma unroll
            for (int n = 0; n < NB; n++) {
                float4 p4 = *(const float4*)&pooled[n][d];
                acch[n] += w4.x * p4.x + w4.y * p4.y + w4.z * p4.z + w4.w * p4.w;
            }
        }
        #pragma unroll
        for (int n = 0; n < NB; n++) s_h[n][tid] = fmaxf(acch[n], 0.f);
    }
    __syncthreads();

    const int warp = tid >> 5, lane = tid & 31;
    for (int n = warp; n < NB; n += 8) {
        float s = 0.f;
        #pragma unroll
        for (int t = lane; t < Hn; t += 32) s += W2[t] * s_h[n][t];
        #pragma unroll
        for (int o = 16; o > 0; o >>= 1) s += __shfl_down_sync(0xffffffffu, s, o);
        if (lane == 0) out[b * NNn + n0 + n] = s + b2[0];
    }
}

// ---------------------------------------------------------------------------
extern "C" void kernel_launch(void* const* d_in, const int* in_sizes, int n_in,
                              void* d_out, int out_size)
{
    const float* articles  = (const float*)d_in[0];
    const int*   nodes_idx = (const int*)  d_in[1];
    const int*   nmask     = (const int*)  d_in[2];
    // d_in[3], d_in[4] (relations) unused: reference discards edges
    const float* W_bert    = (const float*)d_in[5];
    const float* b_bert    = (const float*)d_in[6];
    const float* prelu_a   = (const float*)d_in[7];
    const float* W1        = (const float*)d_in[8];
    const float* b1        = (const float*)d_in[9];
    const float* W2        = (const float*)d_in[10];
    const float* b2        = (const float*)d_in[11];
    float*       out       = (float*)d_out;

    // Idempotent, every call (no static guards).
    cudaFuncSetAttribute(gemm_fused3_kernel,
                         cudaFuncAttributeMaxDynamicSharedMemorySize, SMEMG);

    // Stage 0: W split (4.9us)
    split_w_kernel<<<(NWP4 + 255) / 256, 256>>>(W_bert);

    // Stage 1: fused A-split + wmma GEMM + bias + PReLU (one wave: 128 CTAs)
    dim3 gridG(NPAD / GBN, Mtot / GBM);   // (2, 64)
    gemm_fused3_kernel<<<gridG, 256, SMEMG>>>(articles, b_bert, prelu_a);

    // Stage 2: gather-pool + head
    node_head_kernel<<<(Bn * NNn) / NB, 256>>>(nodes_idx, nmask, W1, b1, W2, b2, out);
}